// round 14
// baseline (speedup 1.0000x reference)
#include <cuda_runtime.h>
#include <cstdint>

#define NN   384
#define HH   128
#define LATD 64
#define RR   16
#define LL   3
#define TT   64
#define MSs  132     // tile row stride (528B = 33*16)
#define RBs  20      // rbf tile row stride
#define RBB  16
#define CUT2 144.0f
#define GAMMA 1.7777778f   // (16/12)^2
#define MUSTEP 0.8f        // 12/15

typedef unsigned long long u64;

// ---------------- device scratch ----------------
__device__ float g_h[NN * HH];
__device__ float g_x[NN * 3];
__device__ float g_base1[NN * HH];
__device__ float g_t1[NN * HH];        // h @ eW1[128:256]  (sender part)
__device__ int   g_nbr[NN * NN];
__device__ float g_dist[NN * NN];
__device__ float g_dvec[NN * NN * 3];
__device__ int   g_cnt[NN];

__device__ __forceinline__ float silu_f(float v) {
    return __fdividef(v, 1.0f + __expf(-v));
}
__device__ __forceinline__ u64 pk2(float x, float y) {
    u64 r; asm("mov.b64 %0,{%1,%2};" : "=l"(r) : "f"(x), "f"(y)); return r;
}
__device__ __forceinline__ u64 fma2(u64 a, u64 b, u64 c) {
    u64 d; asm("fma.rn.f32x2 %0,%1,%2,%3;" : "=l"(d) : "l"(a), "l"(b), "l"(c)); return d;
}
__device__ __forceinline__ float2 upk(u64 a) {
    float2 f; asm("mov.b64 {%0,%1},%2;" : "=f"(f.x), "=f"(f.y) : "l"(a)); return f;
}
__device__ __forceinline__ void cpa16(float* s, const float* g) {
    unsigned sa = (unsigned)__cvta_generic_to_shared(s);
    asm volatile("cp.async.cg.shared.global [%0], [%1], 16;" :: "r"(sa), "l"(g));
}
__device__ __forceinline__ void cpa_commit() { asm volatile("cp.async.commit_group;"); }
template <int W> __device__ __forceinline__ void cpa_wait() {
    asm volatile("cp.async.wait_group %0;" :: "n"(W) : "memory");
}
__device__ __forceinline__ void stage_async(float* dst, const float* src, int nfl, int tid) {
    for (int i = tid * 4; i < nfl; i += 1024) cpa16(dst + i, src + i);
}

// ---------------- init: proj (blocks 0..383) + center (block 384) ----------------
__global__ void k_init(const float* __restrict__ z, const float* __restrict__ W,
                       const float* __restrict__ b, const float* __restrict__ anchor) {
    if (blockIdx.x < NN) {
        __shared__ float zr[LATD];
        int i = blockIdx.x, c = threadIdx.x;
        if (c < LATD) zr[c] = z[i * LATD + c];
        __syncthreads();
        float acc = b[c];
#pragma unroll 8
        for (int k = 0; k < LATD; k++) acc = fmaf(zr[k], W[k * HH + c], acc);
        g_h[i * HH + c] = acc;
    } else {
        __shared__ float part[128][3];
        __shared__ float mean[3];
        int t = threadIdx.x;
        float s0 = 0.f, s1 = 0.f, s2 = 0.f;
        for (int j = t; j < NN; j += 128) {
            s0 += anchor[j * 3 + 0]; s1 += anchor[j * 3 + 1]; s2 += anchor[j * 3 + 2];
        }
        part[t][0] = s0; part[t][1] = s1; part[t][2] = s2;
        __syncthreads();
        if (t < 3) {
            float s = 0.f;
            for (int q = 0; q < 128; q++) s += part[q][t];
            mean[t] = s / (float)NN;
        }
        __syncthreads();
        for (int j = t; j < NN; j += 128) {
            g_x[j * 3 + 0] = anchor[j * 3 + 0] - mean[0];
            g_x[j * 3 + 1] = anchor[j * 3 + 1] - mean[1];
            g_x[j * 3 + 2] = anchor[j * 3 + 2] - mean[2];
        }
    }
}

// ---------------- single-row f32x2 GEMM helper (K=128) ----------------
__device__ __forceinline__ void gemm_row128(u64 acc[4], const float* __restrict__ u0,
                                            const float* __restrict__ w, int cg) {
#pragma unroll 4
    for (int k = 0; k < HH; k += 2) {
        ulonglong2 w0a = *(const ulonglong2*)(w + k * HH + cg);
        ulonglong2 w0b = *(const ulonglong2*)(w + k * HH + cg + 4);
        ulonglong2 w1a = *(const ulonglong2*)(w + (k + 1) * HH + cg);
        ulonglong2 w1b = *(const ulonglong2*)(w + (k + 1) * HH + cg + 4);
        float2 uv = *(const float2*)(u0 + k);
        u64 ua = pk2(uv.x, uv.x), ub = pk2(uv.y, uv.y);
        acc[0] = fma2(ua, w0a.x, acc[0]); acc[1] = fma2(ua, w0a.y, acc[1]);
        acc[2] = fma2(ua, w0b.x, acc[2]); acc[3] = fma2(ua, w0b.y, acc[3]);
        acc[0] = fma2(ub, w1a.x, acc[0]); acc[1] = fma2(ub, w1a.y, acc[1]);
        acc[2] = fma2(ub, w1b.x, acc[2]); acc[3] = fma2(ub, w1b.y, acc[3]);
    }
}

// ---------------- k_prep: graph (blocks<NN) + base1/t1 (blocks>=NN) ----------------
#define SB_PREP ((HH * HH + RBB * HH + HH) * 4)
__global__ __launch_bounds__(256, 2) void k_prep(const float* __restrict__ eW1,
                                                 const float* __restrict__ eb1, int l) {
    extern __shared__ float sb[];
    const int tid = threadIdx.x;
    if (blockIdx.x < NN) {
        int* wcnt  = (int*)sb;
        int* wbase = wcnt + 8;
        int* totalp = wbase + 8;
        const int r = blockIdx.x;
        const int lane = tid & 31, w = tid >> 5;
        const float xi0 = g_x[r * 3 + 0], xi1 = g_x[r * 3 + 1], xi2 = g_x[r * 3 + 2];
        if (tid == 0) *totalp = 0;
        __syncthreads();
        for (int base = 0; base < NN; base += 256) {
            int j = base + tid;
            bool p = false;
            float dx = 0.f, dy = 0.f, dz = 0.f, d2 = 0.f;
            if (j < NN && j != r) {
                dx = xi0 - g_x[j * 3 + 0];
                dy = xi1 - g_x[j * 3 + 1];
                dz = xi2 - g_x[j * 3 + 2];
                d2 = dx * dx + dy * dy + dz * dz;
                p = (d2 < CUT2) || (j == r - 1) || (j == r + 1);
            }
            unsigned bal = __ballot_sync(0xffffffffu, p);
            if (lane == 0) wcnt[w] = __popc(bal);
            __syncthreads();
            if (tid == 0) {
                int run = *totalp;
                for (int q = 0; q < 8; q++) { wbase[q] = run; run += wcnt[q]; }
                *totalp = run;
            }
            __syncthreads();
            if (p) {
                int pos = wbase[w] + __popc(bal & ((1u << lane) - 1u));
                g_nbr[r * NN + pos] = j;
                g_dist[r * NN + pos] = sqrtf(d2);
                g_dvec[(r * NN + pos) * 3 + 0] = dx;
                g_dvec[(r * NN + pos) * 3 + 1] = dy;
                g_dvec[(r * NN + pos) * 3 + 2] = dz;
            }
            __syncthreads();
        }
        if (tid == 0) g_cnt[r] = *totalp;
    } else {
        float* ws = sb;                 // HH*HH
        float* hs = ws + HH * HH;       // RBB*HH
        float* bs = hs + RBB * HH;      // HH
        int r0 = (blockIdx.x - NN) * RBB;
        const float* W = eW1 + (size_t)l * 272 * HH;

        stage_async(ws, W, HH * HH, tid);
        cpa_commit();
        for (int idx = tid; idx < RBB * HH / 4; idx += 256)
            *(float4*)(hs + idx * 4) = *(const float4*)(g_h + r0 * HH + idx * 4);
        if (tid < HH) bs[tid] = eb1[l * HH + tid];
        cpa_wait<0>();
        __syncthreads();

        int r = tid >> 4, cg = (tid & 15) * 8;
        {
            const u64* bp = (const u64*)(bs + cg);
            u64 acc[4] = {bp[0], bp[1], bp[2], bp[3]};
            gemm_row128(acc, hs + r * HH, ws, cg);
            float* d = g_base1 + (r0 + r) * HH + cg;
            float2 t; float4 o0, o1;
            t = upk(acc[0]); o0.x = t.x; o0.y = t.y;
            t = upk(acc[1]); o0.z = t.x; o0.w = t.y;
            t = upk(acc[2]); o1.x = t.x; o1.y = t.y;
            t = upk(acc[3]); o1.z = t.x; o1.w = t.y;
            *(float4*)d = o0; *(float4*)(d + 4) = o1;
        }
        __syncthreads();

        stage_async(ws, W + HH * HH, HH * HH, tid);
        cpa_commit();
        cpa_wait<0>();
        __syncthreads();
        {
            u64 acc[4] = {0ull, 0ull, 0ull, 0ull};
            gemm_row128(acc, hs + r * HH, ws, cg);
            float* d = g_t1 + (r0 + r) * HH + cg;
            float2 t; float4 o0, o1;
            t = upk(acc[0]); o0.x = t.x; o0.y = t.y;
            t = upk(acc[1]); o0.z = t.x; o0.w = t.y;
            t = upk(acc[2]); o1.x = t.x; o1.y = t.y;
            t = upk(acc[3]); o1.z = t.x; o1.w = t.y;
            *(float4*)d = o0; *(float4*)(d + 4) = o1;
        }
    }
}

// ---------------- tile GEMM: warp-per-k-row, 8j x 4c, chunk-4 float4 u loads ----------------
template <int K>
__device__ __forceinline__ void gemmT(const float* __restrict__ u, int ustr,
                                      const float* __restrict__ w,
                                      const float* __restrict__ bias,
                                      float* __restrict__ dst, int dstr,
                                      int tid, int tc) {
    const int wq = tid >> 5, lane = tid & 31;
    const int jr = wq << 3;
    if (jr >= tc) return;
    const int c4 = lane * 4;
    u64 acc[8][2];
    {
        ulonglong2 b = *(const ulonglong2*)(bias + c4);
#pragma unroll
        for (int jj = 0; jj < 8; jj++) { acc[jj][0] = b.x; acc[jj][1] = b.y; }
    }
    const float* u0 = u + jr * ustr;
#pragma unroll 2
    for (int k = 0; k < K; k += 4) {
        ulonglong2 w0 = *(const ulonglong2*)(w + (k + 0) * HH + c4);
        ulonglong2 w1 = *(const ulonglong2*)(w + (k + 1) * HH + c4);
        ulonglong2 w2 = *(const ulonglong2*)(w + (k + 2) * HH + c4);
        ulonglong2 w3 = *(const ulonglong2*)(w + (k + 3) * HH + c4);
#pragma unroll
        for (int jj = 0; jj < 8; jj++) {
            float4 uv = *(const float4*)(u0 + jj * ustr + k);
            u64 a0 = pk2(uv.x, uv.x), a1 = pk2(uv.y, uv.y);
            u64 a2 = pk2(uv.z, uv.z), a3 = pk2(uv.w, uv.w);
            acc[jj][0] = fma2(a0, w0.x, acc[jj][0]);
            acc[jj][1] = fma2(a0, w0.y, acc[jj][1]);
            acc[jj][0] = fma2(a1, w1.x, acc[jj][0]);
            acc[jj][1] = fma2(a1, w1.y, acc[jj][1]);
            acc[jj][0] = fma2(a2, w2.x, acc[jj][0]);
            acc[jj][1] = fma2(a2, w2.y, acc[jj][1]);
            acc[jj][0] = fma2(a3, w3.x, acc[jj][0]);
            acc[jj][1] = fma2(a3, w3.y, acc[jj][1]);
        }
    }
#pragma unroll
    for (int jj = 0; jj < 8; jj++) {
        float2 t0 = upk(acc[jj][0]), t1 = upk(acc[jj][1]);
        float4 o;
        o.x = silu_f(t0.x); o.y = silu_f(t0.y);
        o.z = silu_f(t1.x); o.w = silu_f(t1.y);
        *(float4*)(dst + (jr + jj) * dstr + c4) = o;
    }
}

// ---------------- edge kernel + fused node update: one CTA per receiver ----------------
#define SM_FLOATS (16*HH + HH*HH + HH*HH + TT*MSs + TT*MSs + TT*RBs + 5*HH + 256 + TT*3 + 4)
#define SMEM_EDGE (SM_FLOATS * 4)

__global__ __launch_bounds__(256, 1) void k_edge(
    const float* __restrict__ eW1, const float* __restrict__ eW2,
    const float* __restrict__ eb2, const float* __restrict__ cW1,
    const float* __restrict__ cb1, const float* __restrict__ cW2,
    const float* __restrict__ nW1, const float* __restrict__ nb1,
    const float* __restrict__ nW2, const float* __restrict__ nb2,
    float* __restrict__ out, int l, int last) {
    extern __shared__ float sm[];
    float* wrbf  = sm;                   // 16*HH   (eW1 rbf part, resident)
    float* wb2   = wrbf + 16 * HH;       // HH*HH   (eW2, resident)
    float* wb3   = wb2 + HH * HH;        // HH*HH   (cW1, resident)
    float* m1s   = wb3 + HH * HH;        // TT*MSs  (t1 in -> m1 out; later c1; tail: hs/n1s)
    float* ms    = m1s + TT * MSs;       // TT*MSs  (m; tail: node partials)
    float* rbfs  = ms + TT * MSs;        // TT*RBs
    float* base1 = rbfs + TT * RBs;      // HH
    float* eb2s  = base1 + HH;           // HH
    float* cb1s  = eb2s + HH;            // HH
    float* cW2s  = cb1s + HH;            // HH
    float* aggs  = cW2s + HH;            // HH
    float* part2 = aggs + HH;            // 256
    float* cont  = part2 + 256;          // TT*3
    float* xacc  = cont + TT * 3;        // 4

    const int r = blockIdx.x, tid = threadIdx.x;
    const int wq = tid >> 5, lane = tid & 31;

    stage_async(wrbf, eW1 + ((size_t)l * 272 + 256) * HH, 16 * HH, tid);
    stage_async(wb2, eW2 + (size_t)l * HH * HH, HH * HH, tid);
    stage_async(wb3, cW1 + (size_t)l * HH * HH, HH * HH, tid);
    cpa_commit();

    if (tid < HH) {
        base1[tid] = g_base1[r * HH + tid];
        eb2s[tid]  = eb2[l * HH + tid];
        cb1s[tid]  = cb1[l * HH + tid];
        cW2s[tid]  = cW2[l * HH + tid];
        aggs[tid]  = 0.f;
    }
    if (tid < 3) xacc[tid] = 0.f;
    const int cnt = g_cnt[r];

    for (int t0 = 0; t0 < cnt; t0 += TT) {
        const int tc = min(TT, cnt - t0);
        const int tcr8 = (tc + 7) & ~7;

        for (int idx = tid; idx < tcr8 * 32; idx += 256) {
            int jj = idx >> 5, c16 = (idx & 31) * 4;
            if (jj < tc) {
                int j = g_nbr[r * NN + t0 + jj];
                cpa16(m1s + jj * MSs + c16, g_t1 + j * HH + c16);
            } else {
                *(float4*)(m1s + jj * MSs + c16) = make_float4(0.f, 0.f, 0.f, 0.f);
            }
        }
        cpa_commit();
        for (int idx = tid; idx < tcr8 * RR; idx += 256) {
            int jj = idx >> 4, rb = idx & 15;
            float v = 0.f;
            if (jj < tc) {
                float dd = g_dist[r * NN + t0 + jj] - MUSTEP * (float)rb;
                v = __expf(-GAMMA * dd * dd);
            }
            rbfs[jj * RBs + rb] = v;
        }
        cpa_wait<0>();
        __syncthreads();

        // gemm1 (K=16): m1 = silu(base1 + t1 + rbf @ wrbf), in-place on m1s rows
        {
            const int jr = wq << 3;
            if (jr < tc) {
                const int c4 = lane * 4;
                float4 bb = *(const float4*)(base1 + c4);
                u64 acc[8][2];
#pragma unroll
                for (int jj = 0; jj < 8; jj++) {
                    float4 t = *(const float4*)(m1s + (jr + jj) * MSs + c4);
                    acc[jj][0] = pk2(bb.x + t.x, bb.y + t.y);
                    acc[jj][1] = pk2(bb.z + t.z, bb.w + t.w);
                }
#pragma unroll
                for (int k = 0; k < RR; k += 4) {
                    ulonglong2 w0 = *(const ulonglong2*)(wrbf + (k + 0) * HH + c4);
                    ulonglong2 w1 = *(const ulonglong2*)(wrbf + (k + 1) * HH + c4);
                    ulonglong2 w2 = *(const ulonglong2*)(wrbf + (k + 2) * HH + c4);
                    ulonglong2 w3 = *(const ulonglong2*)(wrbf + (k + 3) * HH + c4);
#pragma unroll
                    for (int jj = 0; jj < 8; jj++) {
                        float4 uv = *(const float4*)(rbfs + (jr + jj) * RBs + k);
                        u64 a0 = pk2(uv.x, uv.x), a1 = pk2(uv.y, uv.y);
                        u64 a2 = pk2(uv.z, uv.z), a3 = pk2(uv.w, uv.w);
                        acc[jj][0] = fma2(a0, w0.x, acc[jj][0]);
                        acc[jj][1] = fma2(a0, w0.y, acc[jj][1]);
                        acc[jj][0] = fma2(a1, w1.x, acc[jj][0]);
                        acc[jj][1] = fma2(a1, w1.y, acc[jj][1]);
                        acc[jj][0] = fma2(a2, w2.x, acc[jj][0]);
                        acc[jj][1] = fma2(a2, w2.y, acc[jj][1]);
                        acc[jj][0] = fma2(a3, w3.x, acc[jj][0]);
                        acc[jj][1] = fma2(a3, w3.y, acc[jj][1]);
                    }
                }
#pragma unroll
                for (int jj = 0; jj < 8; jj++) {
                    float2 t0v = upk(acc[jj][0]), t1v = upk(acc[jj][1]);
                    float4 o;
                    o.x = silu_f(t0v.x); o.y = silu_f(t0v.y);
                    o.z = silu_f(t1v.x); o.w = silu_f(t1v.y);
                    *(float4*)(m1s + (jr + jj) * MSs + c4) = o;
                }
            }
        }
        __syncthreads();

        gemmT<128>(m1s, MSs, wb2, eb2s, ms, MSs, tid, tc);     // m
        __syncthreads();

        {
            int q = tid >> 7, c = tid & 127;
            float s = 0.f;
            for (int jj = q; jj < tc; jj += 2) s += ms[jj * MSs + c];
            part2[q * 128 + c] = s;
        }
        __syncthreads();
        if (tid < HH) aggs[tid] += part2[tid] + part2[128 + tid];

        gemmT<128>(ms, MSs, wb3, cb1s, m1s, MSs, tid, tc);     // c1
        __syncthreads();

        {
            int e = tid >> 2, s4 = tid & 3;
            float s = 0.f;
            if (e < tc) {
                const float* mr = m1s + e * MSs + s4 * 32;
                const float* cw = cW2s + s4 * 32;
#pragma unroll
                for (int q = 0; q < 32; q++) s = fmaf(mr[q], cw[q], s);
            }
            s += __shfl_down_sync(0xffffffffu, s, 2, 4);
            s += __shfl_down_sync(0xffffffffu, s, 1, 4);
            if (s4 == 0) {
                if (e < tc) {
                    const float* dv = g_dvec + (size_t)(r * NN + t0 + e) * 3;
                    cont[e * 3 + 0] = dv[0] * s;
                    cont[e * 3 + 1] = dv[1] * s;
                    cont[e * 3 + 2] = dv[2] * s;
                } else {
                    cont[e * 3 + 0] = 0.f; cont[e * 3 + 1] = 0.f; cont[e * 3 + 2] = 0.f;
                }
            }
        }
        __syncthreads();
        if (tid < 3) {
            float a0 = 0.f, a1 = 0.f, a2 = 0.f, a3 = 0.f;
#pragma unroll
            for (int jj = 0; jj < TT; jj += 4) {
                a0 += cont[(jj + 0) * 3 + tid];
                a1 += cont[(jj + 1) * 3 + tid];
                a2 += cont[(jj + 2) * 3 + tid];
                a3 += cont[(jj + 3) * 3 + tid];
            }
            xacc[tid] += (a0 + a1) + (a2 + a3);
        }
        __syncthreads();
    }

    // ---------- fused node update for receiver r (split-K over 8 warps) ----------
    float* hs    = m1s;            // 128
    float* n1s   = m1s + HH;       // 128
    float* partN = ms;             // 8*HH
    if (tid < HH) hs[tid] = g_h[r * HH + tid];
    __syncthreads();

    const float* W1 = nW1 + (size_t)l * 2 * HH * HH;
    const float* W2 = nW2 + (size_t)l * HH * HH;
    const int kb = wq * 16;
    const int c4 = lane * 4;

    // phase 1: partials of [h|agg] @ W1 over this warp's k-slice
    {
        u64 a0 = 0ull, a1 = 0ull;
#pragma unroll 4
        for (int kk = 0; kk < 16; kk++) {
            int k = kb + kk;
            float4 wv = __ldg((const float4*)(W1 + (size_t)k * HH + c4));
            float hb = hs[k];
            u64 hbb = pk2(hb, hb);
            a0 = fma2(hbb, pk2(wv.x, wv.y), a0);
            a1 = fma2(hbb, pk2(wv.z, wv.w), a1);
            float4 wv2 = __ldg((const float4*)(W1 + (size_t)(HH + k) * HH + c4));
            float ab = aggs[k];
            u64 abb = pk2(ab, ab);
            a0 = fma2(abb, pk2(wv2.x, wv2.y), a0);
            a1 = fma2(abb, pk2(wv2.z, wv2.w), a1);
        }
        float2 t0 = upk(a0), t1 = upk(a1);
        *(float4*)(partN + wq * HH + c4) = make_float4(t0.x, t0.y, t1.x, t1.y);
    }
    __syncthreads();
    if (tid < HH) {
        float s = __ldg(nb1 + l * HH + tid);
#pragma unroll
        for (int q = 0; q < 8; q++) s += partN[q * HH + tid];
        n1s[tid] = silu_f(s);
    }
    __syncthreads();

    // phase 2: partials of n1 @ W2
    {
        u64 a0 = 0ull, a1 = 0ull;
#pragma unroll 4
        for (int kk = 0; kk < 16; kk++) {
            int k = kb + kk;
            float4 wv = __ldg((const float4*)(W2 + (size_t)k * HH + c4));
            float nb = n1s[k];
            u64 nbb = pk2(nb, nb);
            a0 = fma2(nbb, pk2(wv.x, wv.y), a0);
            a1 = fma2(nbb, pk2(wv.z, wv.w), a1);
        }
        float2 t0 = upk(a0), t1 = upk(a1);
        *(float4*)(partN + wq * HH + c4) = make_float4(t0.x, t0.y, t1.x, t1.y);
    }
    __syncthreads();
    if (tid < HH) {
        float s = __ldg(nb2 + l * HH + tid) + hs[tid];
#pragma unroll
        for (int q = 0; q < 8; q++) s += partN[q * HH + tid];
        g_h[r * HH + tid] = s;
    }
    if (tid < 3) {
        float v = g_x[r * 3 + tid] + xacc[tid];
        g_x[r * 3 + tid] = v;
        if (last) out[r * 3 + tid] = v;
    }
}

// ---------------- launch ----------------
extern "C" void kernel_launch(void* const* d_in, const int* in_sizes, int n_in,
                              void* d_out, int out_size) {
    const float* z      = (const float*)d_in[0];
    const float* anchor = (const float*)d_in[1];
    const float* proj_W = (const float*)d_in[2];
    const float* proj_b = (const float*)d_in[3];
    const float* eW1    = (const float*)d_in[4];
    const float* eb1    = (const float*)d_in[5];
    const float* eW2    = (const float*)d_in[6];
    const float* eb2    = (const float*)d_in[7];
    const float* nW1    = (const float*)d_in[8];
    const float* nb1    = (const float*)d_in[9];
    const float* nW2    = (const float*)d_in[10];
    const float* nb2    = (const float*)d_in[11];
    const float* cW1    = (const float*)d_in[12];
    const float* cb1    = (const float*)d_in[13];
    const float* cW2    = (const float*)d_in[14];

    cudaFuncSetAttribute(k_edge, cudaFuncAttributeMaxDynamicSharedMemorySize, SMEM_EDGE);
    cudaFuncSetAttribute(k_prep, cudaFuncAttributeMaxDynamicSharedMemorySize, SB_PREP);

    k_init<<<NN + 1, 128>>>(z, proj_W, proj_b, anchor);
    for (int l = 0; l < LL; l++) {
        k_prep<<<NN + NN / RBB, 256, SB_PREP>>>(eW1, eb1, l);
        k_edge<<<NN, 256, SMEM_EDGE>>>(eW1, eW2, eb2, cW1, cb1, cW2,
                                       nW1, nb1, nW2, nb2,
                                       (float*)d_out, l, l == LL - 1);
    }
}

// round 15
// speedup vs baseline: 1.0865x; 1.0865x over previous
#include <cuda_runtime.h>
#include <cstdint>

#define NN   384
#define HH   128
#define LATD 64
#define RR   16
#define LL   3
#define TT   64
#define MSs  132     // tile row stride (528B = 33*16)
#define RBs  20      // rbf tile row stride
#define RBB  16
#define RBN  3       // k_node rows per CTA (grid 128 = one full wave)
#define CUT2 144.0f
#define GAMMA 1.7777778f   // (16/12)^2
#define MUSTEP 0.8f        // 12/15

typedef unsigned long long u64;

// ---------------- device scratch ----------------
__device__ float g_h[NN * HH];
__device__ float g_x[NN * 3];
__device__ float g_agg[NN * HH];
__device__ float g_xupd[NN * 3];
__device__ float g_base1[NN * HH];
__device__ float g_t1[NN * HH];        // h @ eW1[128:256]  (sender part)
__device__ int   g_nbr[NN * NN];
__device__ float g_dist[NN * NN];
__device__ float g_dvec[NN * NN * 3];
__device__ int   g_cnt[NN];

__device__ __forceinline__ float silu_f(float v) {
    return __fdividef(v, 1.0f + __expf(-v));
}
__device__ __forceinline__ u64 pk2(float x, float y) {
    u64 r; asm("mov.b64 %0,{%1,%2};" : "=l"(r) : "f"(x), "f"(y)); return r;
}
__device__ __forceinline__ u64 fma2(u64 a, u64 b, u64 c) {
    u64 d; asm("fma.rn.f32x2 %0,%1,%2,%3;" : "=l"(d) : "l"(a), "l"(b), "l"(c)); return d;
}
__device__ __forceinline__ float2 upk(u64 a) {
    float2 f; asm("mov.b64 {%0,%1},%2;" : "=f"(f.x), "=f"(f.y) : "l"(a)); return f;
}
__device__ __forceinline__ void cpa16(float* s, const float* g) {
    unsigned sa = (unsigned)__cvta_generic_to_shared(s);
    asm volatile("cp.async.cg.shared.global [%0], [%1], 16;" :: "r"(sa), "l"(g));
}
__device__ __forceinline__ void cpa_commit() { asm volatile("cp.async.commit_group;"); }
template <int W> __device__ __forceinline__ void cpa_wait() {
    asm volatile("cp.async.wait_group %0;" :: "n"(W) : "memory");
}
__device__ __forceinline__ void stage_async(float* dst, const float* src, int nfl, int tid) {
    for (int i = tid * 4; i < nfl; i += 1024) cpa16(dst + i, src + i);
}

// ---------------- init: proj (blocks 0..383) + center (block 384) ----------------
__global__ void k_init(const float* __restrict__ z, const float* __restrict__ W,
                       const float* __restrict__ b, const float* __restrict__ anchor) {
    if (blockIdx.x < NN) {
        __shared__ float zr[LATD];
        int i = blockIdx.x, c = threadIdx.x;
        if (c < LATD) zr[c] = z[i * LATD + c];
        __syncthreads();
        float acc = b[c];
#pragma unroll 8
        for (int k = 0; k < LATD; k++) acc = fmaf(zr[k], W[k * HH + c], acc);
        g_h[i * HH + c] = acc;
    } else {
        __shared__ float part[128][3];
        __shared__ float mean[3];
        int t = threadIdx.x;
        float s0 = 0.f, s1 = 0.f, s2 = 0.f;
        for (int j = t; j < NN; j += 128) {
            s0 += anchor[j * 3 + 0]; s1 += anchor[j * 3 + 1]; s2 += anchor[j * 3 + 2];
        }
        part[t][0] = s0; part[t][1] = s1; part[t][2] = s2;
        __syncthreads();
        if (t < 3) {
            float s = 0.f;
            for (int q = 0; q < 128; q++) s += part[q][t];
            mean[t] = s / (float)NN;
        }
        __syncthreads();
        for (int j = t; j < NN; j += 128) {
            g_x[j * 3 + 0] = anchor[j * 3 + 0] - mean[0];
            g_x[j * 3 + 1] = anchor[j * 3 + 1] - mean[1];
            g_x[j * 3 + 2] = anchor[j * 3 + 2] - mean[2];
        }
    }
}

// ---------------- single-row f32x2 GEMM helper (K=128) ----------------
__device__ __forceinline__ void gemm_row128(u64 acc[4], const float* __restrict__ u0,
                                            const float* __restrict__ w, int cg) {
#pragma unroll 4
    for (int k = 0; k < HH; k += 2) {
        ulonglong2 w0a = *(const ulonglong2*)(w + k * HH + cg);
        ulonglong2 w0b = *(const ulonglong2*)(w + k * HH + cg + 4);
        ulonglong2 w1a = *(const ulonglong2*)(w + (k + 1) * HH + cg);
        ulonglong2 w1b = *(const ulonglong2*)(w + (k + 1) * HH + cg + 4);
        float2 uv = *(const float2*)(u0 + k);
        u64 ua = pk2(uv.x, uv.x), ub = pk2(uv.y, uv.y);
        acc[0] = fma2(ua, w0a.x, acc[0]); acc[1] = fma2(ua, w0a.y, acc[1]);
        acc[2] = fma2(ua, w0b.x, acc[2]); acc[3] = fma2(ua, w0b.y, acc[3]);
        acc[0] = fma2(ub, w1a.x, acc[0]); acc[1] = fma2(ub, w1a.y, acc[1]);
        acc[2] = fma2(ub, w1b.x, acc[2]); acc[3] = fma2(ub, w1b.y, acc[3]);
    }
}

// ---------------- k_prep: graph (blocks<NN) + base1/t1 (blocks>=NN, pipelined) ----------------
#define SB_PREP ((2 * HH * HH + RBB * HH + HH) * 4)
__global__ __launch_bounds__(256, 1) void k_prep(const float* __restrict__ eW1,
                                                 const float* __restrict__ eb1, int l) {
    extern __shared__ float sb[];
    const int tid = threadIdx.x;
    if (blockIdx.x < NN) {
        int* wcnt  = (int*)sb;
        int* wbase = wcnt + 8;
        int* totalp = wbase + 8;
        const int r = blockIdx.x;
        const int lane = tid & 31, w = tid >> 5;
        const float xi0 = g_x[r * 3 + 0], xi1 = g_x[r * 3 + 1], xi2 = g_x[r * 3 + 2];
        if (tid == 0) *totalp = 0;
        __syncthreads();
        for (int base = 0; base < NN; base += 256) {
            int j = base + tid;
            bool p = false;
            float dx = 0.f, dy = 0.f, dz = 0.f, d2 = 0.f;
            if (j < NN && j != r) {
                dx = xi0 - g_x[j * 3 + 0];
                dy = xi1 - g_x[j * 3 + 1];
                dz = xi2 - g_x[j * 3 + 2];
                d2 = dx * dx + dy * dy + dz * dz;
                p = (d2 < CUT2) || (j == r - 1) || (j == r + 1);
            }
            unsigned bal = __ballot_sync(0xffffffffu, p);
            if (lane == 0) wcnt[w] = __popc(bal);
            __syncthreads();
            if (tid == 0) {
                int run = *totalp;
                for (int q = 0; q < 8; q++) { wbase[q] = run; run += wcnt[q]; }
                *totalp = run;
            }
            __syncthreads();
            if (p) {
                int pos = wbase[w] + __popc(bal & ((1u << lane) - 1u));
                g_nbr[r * NN + pos] = j;
                g_dist[r * NN + pos] = sqrtf(d2);
                g_dvec[(r * NN + pos) * 3 + 0] = dx;
                g_dvec[(r * NN + pos) * 3 + 1] = dy;
                g_dvec[(r * NN + pos) * 3 + 2] = dz;
            }
            __syncthreads();
        }
        if (tid == 0) g_cnt[r] = *totalp;
    } else {
        float* ws  = sb;                  // HH*HH  (lo half)
        float* ws2 = ws + HH * HH;        // HH*HH  (hi half)
        float* hs  = ws2 + HH * HH;       // RBB*HH
        float* bs  = hs + RBB * HH;       // HH
        int r0 = (blockIdx.x - NN) * RBB;
        const float* W = eW1 + (size_t)l * 272 * HH;

        stage_async(ws, W, HH * HH, tid);            // group 0: lo
        cpa_commit();
        stage_async(ws2, W + HH * HH, HH * HH, tid); // group 1: hi (streams behind)
        cpa_commit();
        for (int idx = tid; idx < RBB * HH / 4; idx += 256)
            *(float4*)(hs + idx * 4) = *(const float4*)(g_h + r0 * HH + idx * 4);
        if (tid < HH) bs[tid] = eb1[l * HH + tid];
        cpa_wait<1>();    // lo staged
        __syncthreads();

        int r = tid >> 4, cg = (tid & 15) * 8;
        {
            const u64* bp = (const u64*)(bs + cg);
            u64 acc[4] = {bp[0], bp[1], bp[2], bp[3]};
            gemm_row128(acc, hs + r * HH, ws, cg);
            float* d = g_base1 + (r0 + r) * HH + cg;
            float2 t; float4 o0, o1;
            t = upk(acc[0]); o0.x = t.x; o0.y = t.y;
            t = upk(acc[1]); o0.z = t.x; o0.w = t.y;
            t = upk(acc[2]); o1.x = t.x; o1.y = t.y;
            t = upk(acc[3]); o1.z = t.x; o1.w = t.y;
            *(float4*)d = o0; *(float4*)(d + 4) = o1;
        }
        cpa_wait<0>();    // hi staged (mostly overlapped with lo gemm)
        __syncthreads();
        {
            u64 acc[4] = {0ull, 0ull, 0ull, 0ull};
            gemm_row128(acc, hs + r * HH, ws2, cg);
            float* d = g_t1 + (r0 + r) * HH + cg;
            float2 t; float4 o0, o1;
            t = upk(acc[0]); o0.x = t.x; o0.y = t.y;
            t = upk(acc[1]); o0.z = t.x; o0.w = t.y;
            t = upk(acc[2]); o1.x = t.x; o1.y = t.y;
            t = upk(acc[3]); o1.z = t.x; o1.w = t.y;
            *(float4*)d = o0; *(float4*)(d + 4) = o1;
        }
    }
}

// ---------------- tile GEMM: warp-per-k-row, 8j x 4c, chunk-4 float4 u loads ----------------
template <int K>
__device__ __forceinline__ void gemmT(const float* __restrict__ u, int ustr,
                                      const float* __restrict__ w,
                                      const float* __restrict__ bias,
                                      float* __restrict__ dst, int dstr,
                                      int tid, int tc) {
    const int wq = tid >> 5, lane = tid & 31;
    const int jr = wq << 3;
    if (jr >= tc) return;
    const int c4 = lane * 4;
    u64 acc[8][2];
    {
        ulonglong2 b = *(const ulonglong2*)(bias + c4);
#pragma unroll
        for (int jj = 0; jj < 8; jj++) { acc[jj][0] = b.x; acc[jj][1] = b.y; }
    }
    const float* u0 = u + jr * ustr;
#pragma unroll 2
    for (int k = 0; k < K; k += 4) {
        ulonglong2 w0 = *(const ulonglong2*)(w + (k + 0) * HH + c4);
        ulonglong2 w1 = *(const ulonglong2*)(w + (k + 1) * HH + c4);
        ulonglong2 w2 = *(const ulonglong2*)(w + (k + 2) * HH + c4);
        ulonglong2 w3 = *(const ulonglong2*)(w + (k + 3) * HH + c4);
#pragma unroll
        for (int jj = 0; jj < 8; jj++) {
            float4 uv = *(const float4*)(u0 + jj * ustr + k);
            u64 a0 = pk2(uv.x, uv.x), a1 = pk2(uv.y, uv.y);
            u64 a2 = pk2(uv.z, uv.z), a3 = pk2(uv.w, uv.w);
            acc[jj][0] = fma2(a0, w0.x, acc[jj][0]);
            acc[jj][1] = fma2(a0, w0.y, acc[jj][1]);
            acc[jj][0] = fma2(a1, w1.x, acc[jj][0]);
            acc[jj][1] = fma2(a1, w1.y, acc[jj][1]);
            acc[jj][0] = fma2(a2, w2.x, acc[jj][0]);
            acc[jj][1] = fma2(a2, w2.y, acc[jj][1]);
            acc[jj][0] = fma2(a3, w3.x, acc[jj][0]);
            acc[jj][1] = fma2(a3, w3.y, acc[jj][1]);
        }
    }
#pragma unroll
    for (int jj = 0; jj < 8; jj++) {
        float2 t0 = upk(acc[jj][0]), t1 = upk(acc[jj][1]);
        float4 o;
        o.x = silu_f(t0.x); o.y = silu_f(t0.y);
        o.z = silu_f(t1.x); o.w = silu_f(t1.y);
        *(float4*)(dst + (jr + jj) * dstr + c4) = o;
    }
}

// ---------------- edge kernel: one CTA (256 thr) per receiver (R13 champion) ----------------
#define SM_FLOATS (16*HH + HH*HH + HH*HH + TT*MSs + TT*MSs + TT*RBs + 5*HH + 256 + TT*3 + 4)
#define SMEM_EDGE (SM_FLOATS * 4)

__global__ __launch_bounds__(256, 1) void k_edge(
    const float* __restrict__ eW1, const float* __restrict__ eW2,
    const float* __restrict__ eb2, const float* __restrict__ cW1,
    const float* __restrict__ cb1, const float* __restrict__ cW2, int l) {
    extern __shared__ float sm[];
    float* wrbf  = sm;                   // 16*HH   (eW1 rbf part, resident)
    float* wb2   = wrbf + 16 * HH;       // HH*HH   (eW2, resident)
    float* wb3   = wb2 + HH * HH;        // HH*HH   (cW1, resident)
    float* m1s   = wb3 + HH * HH;        // TT*MSs  (t1 in -> m1 out; later c1)
    float* ms    = m1s + TT * MSs;       // TT*MSs  (m)
    float* rbfs  = ms + TT * MSs;        // TT*RBs
    float* base1 = rbfs + TT * RBs;      // HH
    float* eb2s  = base1 + HH;           // HH
    float* cb1s  = eb2s + HH;            // HH
    float* cW2s  = cb1s + HH;            // HH
    float* aggs  = cW2s + HH;            // HH
    float* part2 = aggs + HH;            // 256
    float* cont  = part2 + 256;          // TT*3
    float* xacc  = cont + TT * 3;        // 4

    const int r = blockIdx.x, tid = threadIdx.x;
    const int wq = tid >> 5, lane = tid & 31;

    stage_async(wrbf, eW1 + ((size_t)l * 272 + 256) * HH, 16 * HH, tid);
    stage_async(wb2, eW2 + (size_t)l * HH * HH, HH * HH, tid);
    stage_async(wb3, cW1 + (size_t)l * HH * HH, HH * HH, tid);
    cpa_commit();

    if (tid < HH) {
        base1[tid] = g_base1[r * HH + tid];
        eb2s[tid]  = eb2[l * HH + tid];
        cb1s[tid]  = cb1[l * HH + tid];
        cW2s[tid]  = cW2[l * HH + tid];
        aggs[tid]  = 0.f;
    }
    if (tid < 3) xacc[tid] = 0.f;
    const int cnt = g_cnt[r];

    for (int t0 = 0; t0 < cnt; t0 += TT) {
        const int tc = min(TT, cnt - t0);
        const int tcr8 = (tc + 7) & ~7;

        for (int idx = tid; idx < tcr8 * 32; idx += 256) {
            int jj = idx >> 5, c16 = (idx & 31) * 4;
            if (jj < tc) {
                int j = g_nbr[r * NN + t0 + jj];
                cpa16(m1s + jj * MSs + c16, g_t1 + j * HH + c16);
            } else {
                *(float4*)(m1s + jj * MSs + c16) = make_float4(0.f, 0.f, 0.f, 0.f);
            }
        }
        cpa_commit();
        for (int idx = tid; idx < tcr8 * RR; idx += 256) {
            int jj = idx >> 4, rb = idx & 15;
            float v = 0.f;
            if (jj < tc) {
                float dd = g_dist[r * NN + t0 + jj] - MUSTEP * (float)rb;
                v = __expf(-GAMMA * dd * dd);
            }
            rbfs[jj * RBs + rb] = v;
        }
        cpa_wait<0>();
        __syncthreads();

        // gemm1 (K=16): m1 = silu(base1 + t1 + rbf @ wrbf), in-place on m1s rows
        {
            const int jr = wq << 3;
            if (jr < tc) {
                const int c4 = lane * 4;
                float4 bb = *(const float4*)(base1 + c4);
                u64 acc[8][2];
#pragma unroll
                for (int jj = 0; jj < 8; jj++) {
                    float4 t = *(const float4*)(m1s + (jr + jj) * MSs + c4);
                    acc[jj][0] = pk2(bb.x + t.x, bb.y + t.y);
                    acc[jj][1] = pk2(bb.z + t.z, bb.w + t.w);
                }
#pragma unroll
                for (int k = 0; k < RR; k += 4) {
                    ulonglong2 w0 = *(const ulonglong2*)(wrbf + (k + 0) * HH + c4);
                    ulonglong2 w1 = *(const ulonglong2*)(wrbf + (k + 1) * HH + c4);
                    ulonglong2 w2 = *(const ulonglong2*)(wrbf + (k + 2) * HH + c4);
                    ulonglong2 w3 = *(const ulonglong2*)(wrbf + (k + 3) * HH + c4);
#pragma unroll
                    for (int jj = 0; jj < 8; jj++) {
                        float4 uv = *(const float4*)(rbfs + (jr + jj) * RBs + k);
                        u64 a0 = pk2(uv.x, uv.x), a1 = pk2(uv.y, uv.y);
                        u64 a2 = pk2(uv.z, uv.z), a3 = pk2(uv.w, uv.w);
                        acc[jj][0] = fma2(a0, w0.x, acc[jj][0]);
                        acc[jj][1] = fma2(a0, w0.y, acc[jj][1]);
                        acc[jj][0] = fma2(a1, w1.x, acc[jj][0]);
                        acc[jj][1] = fma2(a1, w1.y, acc[jj][1]);
                        acc[jj][0] = fma2(a2, w2.x, acc[jj][0]);
                        acc[jj][1] = fma2(a2, w2.y, acc[jj][1]);
                        acc[jj][0] = fma2(a3, w3.x, acc[jj][0]);
                        acc[jj][1] = fma2(a3, w3.y, acc[jj][1]);
                    }
                }
#pragma unroll
                for (int jj = 0; jj < 8; jj++) {
                    float2 t0v = upk(acc[jj][0]), t1v = upk(acc[jj][1]);
                    float4 o;
                    o.x = silu_f(t0v.x); o.y = silu_f(t0v.y);
                    o.z = silu_f(t1v.x); o.w = silu_f(t1v.y);
                    *(float4*)(m1s + (jr + jj) * MSs + c4) = o;
                }
            }
        }
        __syncthreads();

        gemmT<128>(m1s, MSs, wb2, eb2s, ms, MSs, tid, tc);     // m
        __syncthreads();

        {
            int q = tid >> 7, c = tid & 127;
            float s = 0.f;
            for (int jj = q; jj < tc; jj += 2) s += ms[jj * MSs + c];
            part2[q * 128 + c] = s;
        }
        __syncthreads();
        if (tid < HH) aggs[tid] += part2[tid] + part2[128 + tid];

        gemmT<128>(ms, MSs, wb3, cb1s, m1s, MSs, tid, tc);     // c1
        __syncthreads();

        {
            int e = tid >> 2, s4 = tid & 3;
            float s = 0.f;
            if (e < tc) {
                const float* mr = m1s + e * MSs + s4 * 32;
                const float* cw = cW2s + s4 * 32;
#pragma unroll
                for (int q = 0; q < 32; q++) s = fmaf(mr[q], cw[q], s);
            }
            s += __shfl_down_sync(0xffffffffu, s, 2, 4);
            s += __shfl_down_sync(0xffffffffu, s, 1, 4);
            if (s4 == 0) {
                if (e < tc) {
                    const float* dv = g_dvec + (size_t)(r * NN + t0 + e) * 3;
                    cont[e * 3 + 0] = dv[0] * s;
                    cont[e * 3 + 1] = dv[1] * s;
                    cont[e * 3 + 2] = dv[2] * s;
                } else {
                    cont[e * 3 + 0] = 0.f; cont[e * 3 + 1] = 0.f; cont[e * 3 + 2] = 0.f;
                }
            }
        }
        __syncthreads();
        if (tid < 3) {
            float a0 = 0.f, a1 = 0.f, a2 = 0.f, a3 = 0.f;
#pragma unroll
            for (int jj = 0; jj < TT; jj += 4) {
                a0 += cont[(jj + 0) * 3 + tid];
                a1 += cont[(jj + 1) * 3 + tid];
                a2 += cont[(jj + 2) * 3 + tid];
                a3 += cont[(jj + 3) * 3 + tid];
            }
            xacc[tid] += (a0 + a1) + (a2 + a3);
        }
        __syncthreads();
    }

    if (tid < HH) g_agg[r * HH + tid] = aggs[tid];
    if (tid < 3) g_xupd[r * 3 + tid] = xacc[tid];
}

// ---------------- k_node: 3 rows/CTA (grid 128 = one wave), split-K over warps ----------------
__global__ __launch_bounds__(256, 4) void k_node(
    const float* __restrict__ nW1, const float* __restrict__ nb1,
    const float* __restrict__ nW2, const float* __restrict__ nb2,
    int l, float* __restrict__ out, int last) {
    __shared__ __align__(16) float hs[RBN * HH];
    __shared__ __align__(16) float as_[RBN * HH];
    __shared__ __align__(16) float n1s[RBN * HH];
    __shared__ __align__(16) float part[8 * RBN * HH];
    __shared__ __align__(16) float b1s[HH], b2s[HH];

    const int tid = threadIdx.x;
    const int w = tid >> 5, lane = tid & 31;
    const int c4 = lane * 4;
    const int r0 = blockIdx.x * RBN;
    const int kb = w * 16;

    if (tid < RBN * 3) {
        int rr = tid / 3, cc = tid - rr * 3;
        float v = g_x[(r0 + rr) * 3 + cc] + g_xupd[(r0 + rr) * 3 + cc];
        g_x[(r0 + rr) * 3 + cc] = v;
        if (last) out[(r0 + rr) * 3 + cc] = v;
    }
    if (tid < RBN * HH / 4) {
        *(float4*)(hs + tid * 4)  = *(const float4*)(g_h + r0 * HH + tid * 4);
        *(float4*)(as_ + tid * 4) = *(const float4*)(g_agg + r0 * HH + tid * 4);
    }
    if (tid < HH) { b1s[tid] = nb1[l * HH + tid]; b2s[tid] = nb2[l * HH + tid]; }
    __syncthreads();

    const float* W1 = nW1 + (size_t)l * 2 * HH * HH;
    const float* W2 = nW2 + (size_t)l * HH * HH;

    // phase 1: partials of [h|agg] @ W1 over this warp's k-slice
    {
        u64 acc[RBN][2];
#pragma unroll
        for (int rr = 0; rr < RBN; rr++) { acc[rr][0] = 0; acc[rr][1] = 0; }
#pragma unroll 4
        for (int kk = 0; kk < 16; kk++) {
            int k = kb + kk;
            float4 wv = __ldg((const float4*)(W1 + (size_t)k * HH + c4));
            u64 w01 = pk2(wv.x, wv.y), w23 = pk2(wv.z, wv.w);
#pragma unroll
            for (int rr = 0; rr < RBN; rr++) {
                float hb = hs[rr * HH + k];
                u64 hbb = pk2(hb, hb);
                acc[rr][0] = fma2(hbb, w01, acc[rr][0]);
                acc[rr][1] = fma2(hbb, w23, acc[rr][1]);
            }
            float4 wv2 = __ldg((const float4*)(W1 + (size_t)(HH + k) * HH + c4));
            u64 v01 = pk2(wv2.x, wv2.y), v23 = pk2(wv2.z, wv2.w);
#pragma unroll
            for (int rr = 0; rr < RBN; rr++) {
                float ab = as_[rr * HH + k];
                u64 abb = pk2(ab, ab);
                acc[rr][0] = fma2(abb, v01, acc[rr][0]);
                acc[rr][1] = fma2(abb, v23, acc[rr][1]);
            }
        }
#pragma unroll
        for (int rr = 0; rr < RBN; rr++) {
            float2 t0 = upk(acc[rr][0]), t1 = upk(acc[rr][1]);
            *(float4*)(part + (w * RBN + rr) * HH + c4) = make_float4(t0.x, t0.y, t1.x, t1.y);
        }
    }
    __syncthreads();
    for (int o = tid; o < RBN * HH; o += 256) {
        int rr = o >> 7, c = o & 127;
        float s = b1s[c];
#pragma unroll
        for (int q = 0; q < 8; q++) s += part[(q * RBN + rr) * HH + c];
        n1s[o] = silu_f(s);
    }
    __syncthreads();

    // phase 2: partials of n1 @ W2
    {
        u64 acc[RBN][2];
#pragma unroll
        for (int rr = 0; rr < RBN; rr++) { acc[rr][0] = 0; acc[rr][1] = 0; }
#pragma unroll 4
        for (int kk = 0; kk < 16; kk++) {
            int k = kb + kk;
            float4 wv = __ldg((const float4*)(W2 + (size_t)k * HH + c4));
            u64 w01 = pk2(wv.x, wv.y), w23 = pk2(wv.z, wv.w);
#pragma unroll
            for (int rr = 0; rr < RBN; rr++) {
                float nb = n1s[rr * HH + k];
                u64 nbb = pk2(nb, nb);
                acc[rr][0] = fma2(nbb, w01, acc[rr][0]);
                acc[rr][1] = fma2(nbb, w23, acc[rr][1]);
            }
        }
#pragma unroll
        for (int rr = 0; rr < RBN; rr++) {
            float2 t0 = upk(acc[rr][0]), t1 = upk(acc[rr][1]);
            *(float4*)(part + (w * RBN + rr) * HH + c4) = make_float4(t0.x, t0.y, t1.x, t1.y);
        }
    }
    __syncthreads();
    for (int o = tid; o < RBN * HH; o += 256) {
        int rr = o >> 7, c = o & 127;
        float s = b2s[c] + hs[o];
#pragma unroll
        for (int q = 0; q < 8; q++) s += part[(q * RBN + rr) * HH + c];
        g_h[(r0 + rr) * HH + c] = s;
    }
}

// ---------------- launch ----------------
extern "C" void kernel_launch(void* const* d_in, const int* in_sizes, int n_in,
                              void* d_out, int out_size) {
    const float* z      = (const float*)d_in[0];
    const float* anchor = (const float*)d_in[1];
    const float* proj_W = (const float*)d_in[2];
    const float* proj_b = (const float*)d_in[3];
    const float* eW1    = (const float*)d_in[4];
    const float* eb1    = (const float*)d_in[5];
    const float* eW2    = (const float*)d_in[6];
    const float* eb2    = (const float*)d_in[7];
    const float* nW1    = (const float*)d_in[8];
    const float* nb1    = (const float*)d_in[9];
    const float* nW2    = (const float*)d_in[10];
    const float* nb2    = (const float*)d_in[11];
    const float* cW1    = (const float*)d_in[12];
    const float* cb1    = (const float*)d_in[13];
    const float* cW2    = (const float*)d_in[14];

    cudaFuncSetAttribute(k_edge, cudaFuncAttributeMaxDynamicSharedMemorySize, SMEM_EDGE);
    cudaFuncSetAttribute(k_prep, cudaFuncAttributeMaxDynamicSharedMemorySize, SB_PREP);

    k_init<<<NN + 1, 128>>>(z, proj_W, proj_b, anchor);
    for (int l = 0; l < LL; l++) {
        k_prep<<<NN + NN / RBB, 256, SB_PREP>>>(eW1, eb1, l);
        k_edge<<<NN, 256, SMEM_EDGE>>>(eW1, eW2, eb2, cW1, cb1, cW2, l);
        k_node<<<NN / RBN, 256>>>(nW1, nb1, nW2, nb2, l, (float*)d_out, l == LL - 1);
    }
}

// round 16
// speedup vs baseline: 1.2920x; 1.1891x over previous
#include <cuda_runtime.h>
#include <cstdint>

#define NN   384
#define HH   128
#define LATD 64
#define RR   16
#define LL   3
#define TT   64
#define MSs  132     // tile row stride (528B = 33*16)
#define RBs  20      // rbf tile row stride
#define RBB  16
#define RBN  3       // k_node rows per CTA (grid 128 = one full wave)
#define CUT2 144.0f
#define GAMMA 1.7777778f   // (16/12)^2
#define MUSTEP 0.8f        // 12/15

typedef unsigned long long u64;

// ---------------- device scratch ----------------
__device__ float g_h[NN * HH];
__device__ float g_x[NN * 3];
__device__ float g_agg[NN * HH];
__device__ float g_xupd[NN * 3];
__device__ float g_base1[NN * HH];
__device__ float g_t1[NN * HH];        // h @ eW1[128:256]  (sender part)
__device__ int   g_nbr[NN * NN];
__device__ float g_dist[NN * NN];
__device__ float g_dvec[NN * NN * 3];
__device__ int   g_cnt[NN];
__device__ int   g_order[NN];          // LPT schedule (cnt descending)

__device__ __forceinline__ float silu_f(float v) {
    return __fdividef(v, 1.0f + __expf(-v));
}
__device__ __forceinline__ u64 pk2(float x, float y) {
    u64 r; asm("mov.b64 %0,{%1,%2};" : "=l"(r) : "f"(x), "f"(y)); return r;
}
__device__ __forceinline__ u64 fma2(u64 a, u64 b, u64 c) {
    u64 d; asm("fma.rn.f32x2 %0,%1,%2,%3;" : "=l"(d) : "l"(a), "l"(b), "l"(c)); return d;
}
__device__ __forceinline__ float2 upk(u64 a) {
    float2 f; asm("mov.b64 {%0,%1},%2;" : "=f"(f.x), "=f"(f.y) : "l"(a)); return f;
}
__device__ __forceinline__ void cpa16(float* s, const float* g) {
    unsigned sa = (unsigned)__cvta_generic_to_shared(s);
    asm volatile("cp.async.cg.shared.global [%0], [%1], 16;" :: "r"(sa), "l"(g));
}
__device__ __forceinline__ void cpa_commit() { asm volatile("cp.async.commit_group;"); }
template <int W> __device__ __forceinline__ void cpa_wait() {
    asm volatile("cp.async.wait_group %0;" :: "n"(W) : "memory");
}
__device__ __forceinline__ void stage_async(float* dst, const float* src, int nfl, int tid) {
    for (int i = tid * 4; i < nfl; i += 1024) cpa16(dst + i, src + i);
}

// ---------------- init: proj (blocks 0..383) + center (block 384) ----------------
__global__ void k_init(const float* __restrict__ z, const float* __restrict__ W,
                       const float* __restrict__ b, const float* __restrict__ anchor) {
    if (blockIdx.x < NN) {
        __shared__ float zr[LATD];
        int i = blockIdx.x, c = threadIdx.x;
        if (c < LATD) zr[c] = z[i * LATD + c];
        __syncthreads();
        float acc = b[c];
#pragma unroll 8
        for (int k = 0; k < LATD; k++) acc = fmaf(zr[k], W[k * HH + c], acc);
        g_h[i * HH + c] = acc;
    } else {
        __shared__ float part[128][3];
        __shared__ float mean[3];
        int t = threadIdx.x;
        float s0 = 0.f, s1 = 0.f, s2 = 0.f;
        for (int j = t; j < NN; j += 128) {
            s0 += anchor[j * 3 + 0]; s1 += anchor[j * 3 + 1]; s2 += anchor[j * 3 + 2];
        }
        part[t][0] = s0; part[t][1] = s1; part[t][2] = s2;
        __syncthreads();
        if (t < 3) {
            float s = 0.f;
            for (int q = 0; q < 128; q++) s += part[q][t];
            mean[t] = s / (float)NN;
        }
        __syncthreads();
        for (int j = t; j < NN; j += 128) {
            g_x[j * 3 + 0] = anchor[j * 3 + 0] - mean[0];
            g_x[j * 3 + 1] = anchor[j * 3 + 1] - mean[1];
            g_x[j * 3 + 2] = anchor[j * 3 + 2] - mean[2];
        }
    }
}

// ---------------- k_sched: stable rank sort by cnt descending (perf-only) ----------------
__global__ void k_sched() {
    __shared__ int keys[NN];
    int tid = threadIdx.x;
    keys[tid] = g_cnt[tid];
    __syncthreads();
    int k = keys[tid];
    int pos = 0;
#pragma unroll 8
    for (int q = 0; q < NN; q++) {
        int kq = keys[q];
        pos += (kq > k) || (kq == k && q < tid);
    }
    g_order[pos] = tid;
}

// ---------------- single-row f32x2 GEMM helper (K=128) ----------------
__device__ __forceinline__ void gemm_row128(u64 acc[4], const float* __restrict__ u0,
                                            const float* __restrict__ w, int cg) {
#pragma unroll 4
    for (int k = 0; k < HH; k += 2) {
        ulonglong2 w0a = *(const ulonglong2*)(w + k * HH + cg);
        ulonglong2 w0b = *(const ulonglong2*)(w + k * HH + cg + 4);
        ulonglong2 w1a = *(const ulonglong2*)(w + (k + 1) * HH + cg);
        ulonglong2 w1b = *(const ulonglong2*)(w + (k + 1) * HH + cg + 4);
        float2 uv = *(const float2*)(u0 + k);
        u64 ua = pk2(uv.x, uv.x), ub = pk2(uv.y, uv.y);
        acc[0] = fma2(ua, w0a.x, acc[0]); acc[1] = fma2(ua, w0a.y, acc[1]);
        acc[2] = fma2(ua, w0b.x, acc[2]); acc[3] = fma2(ua, w0b.y, acc[3]);
        acc[0] = fma2(ub, w1a.x, acc[0]); acc[1] = fma2(ub, w1a.y, acc[1]);
        acc[2] = fma2(ub, w1b.x, acc[2]); acc[3] = fma2(ub, w1b.y, acc[3]);
    }
}

// ---------------- k_prep: graph (blocks<NN) + base1/t1 (blocks>=NN, pipelined) ----------------
#define SB_PREP ((2 * HH * HH + RBB * HH + HH) * 4)
__global__ __launch_bounds__(256, 1) void k_prep(const float* __restrict__ eW1,
                                                 const float* __restrict__ eb1, int l) {
    extern __shared__ float sb[];
    const int tid = threadIdx.x;
    if (blockIdx.x < NN) {
        int* wcnt  = (int*)sb;
        int* wbase = wcnt + 8;
        int* totalp = wbase + 8;
        const int r = blockIdx.x;
        const int lane = tid & 31, w = tid >> 5;
        const float xi0 = g_x[r * 3 + 0], xi1 = g_x[r * 3 + 1], xi2 = g_x[r * 3 + 2];
        if (tid == 0) *totalp = 0;
        __syncthreads();
        for (int base = 0; base < NN; base += 256) {
            int j = base + tid;
            bool p = false;
            float dx = 0.f, dy = 0.f, dz = 0.f, d2 = 0.f;
            if (j < NN && j != r) {
                dx = xi0 - g_x[j * 3 + 0];
                dy = xi1 - g_x[j * 3 + 1];
                dz = xi2 - g_x[j * 3 + 2];
                d2 = dx * dx + dy * dy + dz * dz;
                p = (d2 < CUT2) || (j == r - 1) || (j == r + 1);
            }
            unsigned bal = __ballot_sync(0xffffffffu, p);
            if (lane == 0) wcnt[w] = __popc(bal);
            __syncthreads();
            if (tid == 0) {
                int run = *totalp;
                for (int q = 0; q < 8; q++) { wbase[q] = run; run += wcnt[q]; }
                *totalp = run;
            }
            __syncthreads();
            if (p) {
                int pos = wbase[w] + __popc(bal & ((1u << lane) - 1u));
                g_nbr[r * NN + pos] = j;
                g_dist[r * NN + pos] = sqrtf(d2);
                g_dvec[(r * NN + pos) * 3 + 0] = dx;
                g_dvec[(r * NN + pos) * 3 + 1] = dy;
                g_dvec[(r * NN + pos) * 3 + 2] = dz;
            }
            __syncthreads();
        }
        if (tid == 0) g_cnt[r] = *totalp;
    } else {
        float* ws  = sb;                  // HH*HH  (lo half)
        float* ws2 = ws + HH * HH;        // HH*HH  (hi half)
        float* hs  = ws2 + HH * HH;       // RBB*HH
        float* bs  = hs + RBB * HH;       // HH
        int r0 = (blockIdx.x - NN) * RBB;
        const float* W = eW1 + (size_t)l * 272 * HH;

        stage_async(ws, W, HH * HH, tid);            // group 0: lo
        cpa_commit();
        stage_async(ws2, W + HH * HH, HH * HH, tid); // group 1: hi (streams behind)
        cpa_commit();
        for (int idx = tid; idx < RBB * HH / 4; idx += 256)
            *(float4*)(hs + idx * 4) = *(const float4*)(g_h + r0 * HH + idx * 4);
        if (tid < HH) bs[tid] = eb1[l * HH + tid];
        cpa_wait<1>();    // lo staged
        __syncthreads();

        int r = tid >> 4, cg = (tid & 15) * 8;
        {
            const u64* bp = (const u64*)(bs + cg);
            u64 acc[4] = {bp[0], bp[1], bp[2], bp[3]};
            gemm_row128(acc, hs + r * HH, ws, cg);
            float* d = g_base1 + (r0 + r) * HH + cg;
            float2 t; float4 o0, o1;
            t = upk(acc[0]); o0.x = t.x; o0.y = t.y;
            t = upk(acc[1]); o0.z = t.x; o0.w = t.y;
            t = upk(acc[2]); o1.x = t.x; o1.y = t.y;
            t = upk(acc[3]); o1.z = t.x; o1.w = t.y;
            *(float4*)d = o0; *(float4*)(d + 4) = o1;
        }
        cpa_wait<0>();    // hi staged (mostly overlapped with lo gemm)
        __syncthreads();
        {
            u64 acc[4] = {0ull, 0ull, 0ull, 0ull};
            gemm_row128(acc, hs + r * HH, ws2, cg);
            float* d = g_t1 + (r0 + r) * HH + cg;
            float2 t; float4 o0, o1;
            t = upk(acc[0]); o0.x = t.x; o0.y = t.y;
            t = upk(acc[1]); o0.z = t.x; o0.w = t.y;
            t = upk(acc[2]); o1.x = t.x; o1.y = t.y;
            t = upk(acc[3]); o1.z = t.x; o1.w = t.y;
            *(float4*)d = o0; *(float4*)(d + 4) = o1;
        }
    }
}

// ---------------- tile GEMM: warp-per-k-row, 8j x 4c, chunk-4 float4 u loads ----------------
template <int K>
__device__ __forceinline__ void gemmT(const float* __restrict__ u, int ustr,
                                      const float* __restrict__ w,
                                      const float* __restrict__ bias,
                                      float* __restrict__ dst, int dstr,
                                      int tid, int tc) {
    const int wq = tid >> 5, lane = tid & 31;
    const int jr = wq << 3;
    if (jr >= tc) return;
    const int c4 = lane * 4;
    u64 acc[8][2];
    {
        ulonglong2 b = *(const ulonglong2*)(bias + c4);
#pragma unroll
        for (int jj = 0; jj < 8; jj++) { acc[jj][0] = b.x; acc[jj][1] = b.y; }
    }
    const float* u0 = u + jr * ustr;
#pragma unroll 2
    for (int k = 0; k < K; k += 4) {
        ulonglong2 w0 = *(const ulonglong2*)(w + (k + 0) * HH + c4);
        ulonglong2 w1 = *(const ulonglong2*)(w + (k + 1) * HH + c4);
        ulonglong2 w2 = *(const ulonglong2*)(w + (k + 2) * HH + c4);
        ulonglong2 w3 = *(const ulonglong2*)(w + (k + 3) * HH + c4);
#pragma unroll
        for (int jj = 0; jj < 8; jj++) {
            float4 uv = *(const float4*)(u0 + jj * ustr + k);
            u64 a0 = pk2(uv.x, uv.x), a1 = pk2(uv.y, uv.y);
            u64 a2 = pk2(uv.z, uv.z), a3 = pk2(uv.w, uv.w);
            acc[jj][0] = fma2(a0, w0.x, acc[jj][0]);
            acc[jj][1] = fma2(a0, w0.y, acc[jj][1]);
            acc[jj][0] = fma2(a1, w1.x, acc[jj][0]);
            acc[jj][1] = fma2(a1, w1.y, acc[jj][1]);
            acc[jj][0] = fma2(a2, w2.x, acc[jj][0]);
            acc[jj][1] = fma2(a2, w2.y, acc[jj][1]);
            acc[jj][0] = fma2(a3, w3.x, acc[jj][0]);
            acc[jj][1] = fma2(a3, w3.y, acc[jj][1]);
        }
    }
#pragma unroll
    for (int jj = 0; jj < 8; jj++) {
        float2 t0 = upk(acc[jj][0]), t1 = upk(acc[jj][1]);
        float4 o;
        o.x = silu_f(t0.x); o.y = silu_f(t0.y);
        o.z = silu_f(t1.x); o.w = silu_f(t1.y);
        *(float4*)(dst + (jr + jj) * dstr + c4) = o;
    }
}

// ---------------- edge kernel: one CTA (256 thr) per receiver, LPT order ----------------
#define SM_FLOATS (16*HH + HH*HH + HH*HH + TT*MSs + TT*MSs + TT*RBs + 5*HH + 256 + TT*3 + 4)
#define SMEM_EDGE (SM_FLOATS * 4)

__global__ __launch_bounds__(256, 1) void k_edge(
    const float* __restrict__ eW1, const float* __restrict__ eW2,
    const float* __restrict__ eb2, const float* __restrict__ cW1,
    const float* __restrict__ cb1, const float* __restrict__ cW2, int l) {
    extern __shared__ float sm[];
    float* wrbf  = sm;                   // 16*HH   (eW1 rbf part, resident)
    float* wb2   = wrbf + 16 * HH;       // HH*HH   (eW2, resident)
    float* wb3   = wb2 + HH * HH;        // HH*HH   (cW1, resident)
    float* m1s   = wb3 + HH * HH;        // TT*MSs  (t1 in -> m1 out; later c1)
    float* ms    = m1s + TT * MSs;       // TT*MSs  (m)
    float* rbfs  = ms + TT * MSs;        // TT*RBs
    float* base1 = rbfs + TT * RBs;      // HH
    float* eb2s  = base1 + HH;           // HH
    float* cb1s  = eb2s + HH;            // HH
    float* cW2s  = cb1s + HH;            // HH
    float* aggs  = cW2s + HH;            // HH
    float* part2 = aggs + HH;            // 256
    float* cont  = part2 + 256;          // TT*3
    float* xacc  = cont + TT * 3;        // 4

    const int r = g_order[blockIdx.x];   // LPT schedule (long jobs first)
    const int tid = threadIdx.x;
    const int wq = tid >> 5, lane = tid & 31;

    stage_async(wrbf, eW1 + ((size_t)l * 272 + 256) * HH, 16 * HH, tid);
    stage_async(wb2, eW2 + (size_t)l * HH * HH, HH * HH, tid);
    stage_async(wb3, cW1 + (size_t)l * HH * HH, HH * HH, tid);
    cpa_commit();

    if (tid < HH) {
        base1[tid] = g_base1[r * HH + tid];
        eb2s[tid]  = eb2[l * HH + tid];
        cb1s[tid]  = cb1[l * HH + tid];
        cW2s[tid]  = cW2[l * HH + tid];
        aggs[tid]  = 0.f;
    }
    if (tid < 3) xacc[tid] = 0.f;
    const int cnt = g_cnt[r];

    for (int t0 = 0; t0 < cnt; t0 += TT) {
        const int tc = min(TT, cnt - t0);
        const int tcr8 = (tc + 7) & ~7;

        for (int idx = tid; idx < tcr8 * 32; idx += 256) {
            int jj = idx >> 5, c16 = (idx & 31) * 4;
            if (jj < tc) {
                int j = g_nbr[r * NN + t0 + jj];
                cpa16(m1s + jj * MSs + c16, g_t1 + j * HH + c16);
            } else {
                *(float4*)(m1s + jj * MSs + c16) = make_float4(0.f, 0.f, 0.f, 0.f);
            }
        }
        cpa_commit();
        for (int idx = tid; idx < tcr8 * RR; idx += 256) {
            int jj = idx >> 4, rb = idx & 15;
            float v = 0.f;
            if (jj < tc) {
                float dd = g_dist[r * NN + t0 + jj] - MUSTEP * (float)rb;
                v = __expf(-GAMMA * dd * dd);
            }
            rbfs[jj * RBs + rb] = v;
        }
        cpa_wait<0>();
        __syncthreads();

        // gemm1 (K=16): m1 = silu(base1 + t1 + rbf @ wrbf), in-place on m1s rows
        {
            const int jr = wq << 3;
            if (jr < tc) {
                const int c4 = lane * 4;
                float4 bb = *(const float4*)(base1 + c4);
                u64 acc[8][2];
#pragma unroll
                for (int jj = 0; jj < 8; jj++) {
                    float4 t = *(const float4*)(m1s + (jr + jj) * MSs + c4);
                    acc[jj][0] = pk2(bb.x + t.x, bb.y + t.y);
                    acc[jj][1] = pk2(bb.z + t.z, bb.w + t.w);
                }
#pragma unroll
                for (int k = 0; k < RR; k += 4) {
                    ulonglong2 w0 = *(const ulonglong2*)(wrbf + (k + 0) * HH + c4);
                    ulonglong2 w1 = *(const ulonglong2*)(wrbf + (k + 1) * HH + c4);
                    ulonglong2 w2 = *(const ulonglong2*)(wrbf + (k + 2) * HH + c4);
                    ulonglong2 w3 = *(const ulonglong2*)(wrbf + (k + 3) * HH + c4);
#pragma unroll
                    for (int jj = 0; jj < 8; jj++) {
                        float4 uv = *(const float4*)(rbfs + (jr + jj) * RBs + k);
                        u64 a0 = pk2(uv.x, uv.x), a1 = pk2(uv.y, uv.y);
                        u64 a2 = pk2(uv.z, uv.z), a3 = pk2(uv.w, uv.w);
                        acc[jj][0] = fma2(a0, w0.x, acc[jj][0]);
                        acc[jj][1] = fma2(a0, w0.y, acc[jj][1]);
                        acc[jj][0] = fma2(a1, w1.x, acc[jj][0]);
                        acc[jj][1] = fma2(a1, w1.y, acc[jj][1]);
                        acc[jj][0] = fma2(a2, w2.x, acc[jj][0]);
                        acc[jj][1] = fma2(a2, w2.y, acc[jj][1]);
                        acc[jj][0] = fma2(a3, w3.x, acc[jj][0]);
                        acc[jj][1] = fma2(a3, w3.y, acc[jj][1]);
                    }
                }
#pragma unroll
                for (int jj = 0; jj < 8; jj++) {
                    float2 t0v = upk(acc[jj][0]), t1v = upk(acc[jj][1]);
                    float4 o;
                    o.x = silu_f(t0v.x); o.y = silu_f(t0v.y);
                    o.z = silu_f(t1v.x); o.w = silu_f(t1v.y);
                    *(float4*)(m1s + (jr + jj) * MSs + c4) = o;
                }
            }
        }
        __syncthreads();

        gemmT<128>(m1s, MSs, wb2, eb2s, ms, MSs, tid, tc);     // m
        __syncthreads();

        {
            int q = tid >> 7, c = tid & 127;
            float s = 0.f;
            for (int jj = q; jj < tc; jj += 2) s += ms[jj * MSs + c];
            part2[q * 128 + c] = s;
        }
        __syncthreads();
        if (tid < HH) aggs[tid] += part2[tid] + part2[128 + tid];

        gemmT<128>(ms, MSs, wb3, cb1s, m1s, MSs, tid, tc);     // c1
        __syncthreads();

        {
            int e = tid >> 2, s4 = tid & 3;
            float s = 0.f;
            if (e < tc) {
                const float* mr = m1s + e * MSs + s4 * 32;
                const float* cw = cW2s + s4 * 32;
#pragma unroll
                for (int q = 0; q < 32; q++) s = fmaf(mr[q], cw[q], s);
            }
            s += __shfl_down_sync(0xffffffffu, s, 2, 4);
            s += __shfl_down_sync(0xffffffffu, s, 1, 4);
            if (s4 == 0) {
                if (e < tc) {
                    const float* dv = g_dvec + (size_t)(r * NN + t0 + e) * 3;
                    cont[e * 3 + 0] = dv[0] * s;
                    cont[e * 3 + 1] = dv[1] * s;
                    cont[e * 3 + 2] = dv[2] * s;
                } else {
                    cont[e * 3 + 0] = 0.f; cont[e * 3 + 1] = 0.f; cont[e * 3 + 2] = 0.f;
                }
            }
        }
        __syncthreads();
        if (tid < 3) {
            float a0 = 0.f, a1 = 0.f, a2 = 0.f, a3 = 0.f;
#pragma unroll
            for (int jj = 0; jj < TT; jj += 4) {
                a0 += cont[(jj + 0) * 3 + tid];
                a1 += cont[(jj + 1) * 3 + tid];
                a2 += cont[(jj + 2) * 3 + tid];
                a3 += cont[(jj + 3) * 3 + tid];
            }
            xacc[tid] += (a0 + a1) + (a2 + a3);
        }
        __syncthreads();
    }

    if (tid < HH) g_agg[r * HH + tid] = aggs[tid];
    if (tid < 3) g_xupd[r * 3 + tid] = xacc[tid];
}

// ---------------- k_node: 3 rows/CTA (grid 128 = one wave), split-K over warps ----------------
__global__ __launch_bounds__(256, 4) void k_node(
    const float* __restrict__ nW1, const float* __restrict__ nb1,
    const float* __restrict__ nW2, const float* __restrict__ nb2,
    int l, float* __restrict__ out, int last) {
    __shared__ __align__(16) float hs[RBN * HH];
    __shared__ __align__(16) float as_[RBN * HH];
    __shared__ __align__(16) float n1s[RBN * HH];
    __shared__ __align__(16) float part[8 * RBN * HH];
    __shared__ __align__(16) float b1s[HH], b2s[HH];

    const int tid = threadIdx.x;
    const int w = tid >> 5, lane = tid & 31;
    const int c4 = lane * 4;
    const int r0 = blockIdx.x * RBN;
    const int kb = w * 16;

    if (tid < RBN * 3) {
        int rr = tid / 3, cc = tid - rr * 3;
        float v = g_x[(r0 + rr) * 3 + cc] + g_xupd[(r0 + rr) * 3 + cc];
        g_x[(r0 + rr) * 3 + cc] = v;
        if (last) out[(r0 + rr) * 3 + cc] = v;
    }
    if (tid < RBN * HH / 4) {
        *(float4*)(hs + tid * 4)  = *(const float4*)(g_h + r0 * HH + tid * 4);
        *(float4*)(as_ + tid * 4) = *(const float4*)(g_agg + r0 * HH + tid * 4);
    }
    if (tid < HH) { b1s[tid] = nb1[l * HH + tid]; b2s[tid] = nb2[l * HH + tid]; }
    __syncthreads();

    const float* W1 = nW1 + (size_t)l * 2 * HH * HH;
    const float* W2 = nW2 + (size_t)l * HH * HH;

    // phase 1: partials of [h|agg] @ W1 over this warp's k-slice
    {
        u64 acc[RBN][2];
#pragma unroll
        for (int rr = 0; rr < RBN; rr++) { acc[rr][0] = 0; acc[rr][1] = 0; }
#pragma unroll 4
        for (int kk = 0; kk < 16; kk++) {
            int k = kb + kk;
            float4 wv = __ldg((const float4*)(W1 + (size_t)k * HH + c4));
            u64 w01 = pk2(wv.x, wv.y), w23 = pk2(wv.z, wv.w);
#pragma unroll
            for (int rr = 0; rr < RBN; rr++) {
                float hb = hs[rr * HH + k];
                u64 hbb = pk2(hb, hb);
                acc[rr][0] = fma2(hbb, w01, acc[rr][0]);
                acc[rr][1] = fma2(hbb, w23, acc[rr][1]);
            }
            float4 wv2 = __ldg((const float4*)(W1 + (size_t)(HH + k) * HH + c4));
            u64 v01 = pk2(wv2.x, wv2.y), v23 = pk2(wv2.z, wv2.w);
#pragma unroll
            for (int rr = 0; rr < RBN; rr++) {
                float ab = as_[rr * HH + k];
                u64 abb = pk2(ab, ab);
                acc[rr][0] = fma2(abb, v01, acc[rr][0]);
                acc[rr][1] = fma2(abb, v23, acc[rr][1]);
            }
        }
#pragma unroll
        for (int rr = 0; rr < RBN; rr++) {
            float2 t0 = upk(acc[rr][0]), t1 = upk(acc[rr][1]);
            *(float4*)(part + (w * RBN + rr) * HH + c4) = make_float4(t0.x, t0.y, t1.x, t1.y);
        }
    }
    __syncthreads();
    for (int o = tid; o < RBN * HH; o += 256) {
        int rr = o >> 7, c = o & 127;
        float s = b1s[c];
#pragma unroll
        for (int q = 0; q < 8; q++) s += part[(q * RBN + rr) * HH + c];
        n1s[o] = silu_f(s);
    }
    __syncthreads();

    // phase 2: partials of n1 @ W2
    {
        u64 acc[RBN][2];
#pragma unroll
        for (int rr = 0; rr < RBN; rr++) { acc[rr][0] = 0; acc[rr][1] = 0; }
#pragma unroll 4
        for (int kk = 0; kk < 16; kk++) {
            int k = kb + kk;
            float4 wv = __ldg((const float4*)(W2 + (size_t)k * HH + c4));
            u64 w01 = pk2(wv.x, wv.y), w23 = pk2(wv.z, wv.w);
#pragma unroll
            for (int rr = 0; rr < RBN; rr++) {
                float nb = n1s[rr * HH + k];
                u64 nbb = pk2(nb, nb);
                acc[rr][0] = fma2(nbb, w01, acc[rr][0]);
                acc[rr][1] = fma2(nbb, w23, acc[rr][1]);
            }
        }
#pragma unroll
        for (int rr = 0; rr < RBN; rr++) {
            float2 t0 = upk(acc[rr][0]), t1 = upk(acc[rr][1]);
            *(float4*)(part + (w * RBN + rr) * HH + c4) = make_float4(t0.x, t0.y, t1.x, t1.y);
        }
    }
    __syncthreads();
    for (int o = tid; o < RBN * HH; o += 256) {
        int rr = o >> 7, c = o & 127;
        float s = b2s[c] + hs[o];
#pragma unroll
        for (int q = 0; q < 8; q++) s += part[(q * RBN + rr) * HH + c];
        g_h[(r0 + rr) * HH + c] = s;
    }
}

// ---------------- launch ----------------
extern "C" void kernel_launch(void* const* d_in, const int* in_sizes, int n_in,
                              void* d_out, int out_size) {
    const float* z      = (const float*)d_in[0];
    const float* anchor = (const float*)d_in[1];
    const float* proj_W = (const float*)d_in[2];
    const float* proj_b = (const float*)d_in[3];
    const float* eW1    = (const float*)d_in[4];
    const float* eb1    = (const float*)d_in[5];
    const float* eW2    = (const float*)d_in[6];
    const float* eb2    = (const float*)d_in[7];
    const float* nW1    = (const float*)d_in[8];
    const float* nb1    = (const float*)d_in[9];
    const float* nW2    = (const float*)d_in[10];
    const float* nb2    = (const float*)d_in[11];
    const float* cW1    = (const float*)d_in[12];
    const float* cb1    = (const float*)d_in[13];
    const float* cW2    = (const float*)d_in[14];

    cudaFuncSetAttribute(k_edge, cudaFuncAttributeMaxDynamicSharedMemorySize, SMEM_EDGE);
    cudaFuncSetAttribute(k_prep, cudaFuncAttributeMaxDynamicSharedMemorySize, SB_PREP);

    k_init<<<NN + 1, 128>>>(z, proj_W, proj_b, anchor);
    for (int l = 0; l < LL; l++) {
        k_prep<<<NN + NN / RBB, 256, SB_PREP>>>(eW1, eb1, l);
        if (l == 0) k_sched<<<1, NN>>>();   // LPT order (reused across layers; perf-only)
        k_edge<<<NN, 256, SMEM_EDGE>>>(eW1, eW2, eb2, cW1, cb1, cW2, l);
        k_node<<<NN / RBN, 256>>>(nW1, nb1, nW2, nb2, l, (float*)d_out, l == LL - 1);
    }
}